// round 8
// baseline (speedup 1.0000x reference)
#include <cuda_runtime.h>

// x (1,128,56,56) f32, W (32,64,3) f32 -> out (1,32,56,56) f32
//   t2[c,h,w]  = x[c,h,w] + x[c+64,h,w]
//   out[i,h,w] = sum_{c,k} t2[c, h+k-1, w] * W[i,c,k]   (3-tap H conv, zero pad)
//   store rolled +1 along w.
//
// Layout: W row i natively ordered j = c*3+k; taps staged as t3[w][j] so both
// main-loop operands are contiguous. Main loop uses packed fma.rn.f32x2
// (2 fp32 FMA per instr, PTX-only) -> 96 LDS.128 + 96 FFMA2 per thread.

#define TILE_W 7
#define RLEN   192          // 64 c * 3 k
#define RPAD   196          // row stride 784B (16B-aligned); lanes land on distinct bank quads
#define NTHR   224          // 7 x 32

typedef unsigned long long u64t;

__device__ __forceinline__ void ffma2(u64t& d, u64t a, u64t b) {
    // two independent fp32 FMAs on packed f32x2 (bit-exact vs scalar fmaf)
    asm("fma.rn.f32x2 %0, %1, %2, %0;" : "+l"(d) : "l"(a), "l"(b));
}

__global__ __launch_bounds__(NTHR, 3)
void fused_pairconv_roll(const float* __restrict__ x,
                         const float* __restrict__ W,
                         float* __restrict__ out)
{
    __shared__ __align__(16) float sh_t3[TILE_W * RPAD];   // [w][j]  5.5 KB
    __shared__ __align__(16) float sh_W [32 * RPAD];       // [i][j] 25.1 KB

    const int h   = blockIdx.y;             // 0..55
    const int w0  = blockIdx.x * TILE_W;    // 0,7,...,49
    const int tx  = threadIdx.x;            // w within tile (7)
    const int ty  = threadIdx.y;            // i (32)
    const int tid = tx + ty * TILE_W;       // 0..223

    // ---- Phase A: issue ALL tap LDGs up front (predicated, branch-free) ----
    float xa[6], xb[6];
    #pragma unroll
    for (int it = 0; it < 6; ++it) {
        int j   = ty + 32 * it;                 // 0..191
        int c   = j / 3;                        // mul-shift
        int k   = j - 3 * c;
        int row = h - 1 + k;
        bool ok = (row >= 0) && (row < 56);
        int base = (ok ? row : 0) * 56 + (w0 + tx);
        xa[it] = ok ? __ldg(&x[c * 3136 + base])        : 0.0f;
        xb[it] = ok ? __ldg(&x[(c + 64) * 3136 + base]) : 0.0f;
    }

    // ---- Phase B: W copy overlaps the in-flight tap LDGs (native order) ----
    {
        const float4* __restrict__ Wf4 = (const float4*)W;
        #pragma unroll
        for (int it = 0; it < 7; ++it) {
            int idx = tid + it * NTHR;          // < 1536
            if (idx < 1536) {
                int i  = idx / 48;
                int jj = idx - i * 48;
                ((float4*)sh_W)[i * (RPAD / 4) + jj] = Wf4[idx];
            }
        }
    }

    // ---- Phase C: combine taps, store to shared ----
    #pragma unroll
    for (int it = 0; it < 6; ++it) {
        int j = ty + 32 * it;
        sh_t3[tx * RPAD + j] = xa[it] + xb[it];
    }
    __syncthreads();

    // ---- Main loop: one output per thread (i = ty, h, w = w0 + tx) ----
    const ulonglong2* __restrict__ t3p = (const ulonglong2*)&sh_t3[tx * RPAD];
    const ulonglong2* __restrict__ wp  = (const ulonglong2*)&sh_W [ty * RPAD];

    u64t acc0 = 0ull, acc1 = 0ull, acc2 = 0ull, acc3 = 0ull;   // packed {0,0}
    #pragma unroll
    for (int q = 0; q < RLEN / 8; ++q) {        // 24 steps, 2 float4-pairs each
        ulonglong2 a0 = t3p[2 * q];
        ulonglong2 b0 = wp [2 * q];
        ulonglong2 a1 = t3p[2 * q + 1];
        ulonglong2 b1 = wp [2 * q + 1];
        ffma2(acc0, a0.x, b0.x);
        ffma2(acc1, a0.y, b0.y);
        ffma2(acc2, a1.x, b1.x);
        ffma2(acc3, a1.y, b1.y);
    }

    float2 f0 = *(float2*)&acc0;
    float2 f1 = *(float2*)&acc1;
    float2 f2 = *(float2*)&acc2;
    float2 f3 = *(float2*)&acc3;
    float r = ((f0.x + f0.y) + (f1.x + f1.y)) + ((f2.x + f2.y) + (f3.x + f3.y));

    const int w    = w0 + tx;
    const int wout = (w + 1 < 56) ? (w + 1) : 0;   // roll +1 along width
    out[ty * 3136 + h * 56 + wout] = r;
}

extern "C" void kernel_launch(void* const* d_in, const int* in_sizes, int n_in,
                              void* d_out, int out_size)
{
    // Resolve inputs by size (x = 401408, W = 6144)
    const float* x = (const float*)d_in[0];
    const float* W = (const float*)d_in[1];
    if (n_in >= 2 && in_sizes[0] == 6144 && in_sizes[1] == 401408) {
        x = (const float*)d_in[1];
        W = (const float*)d_in[0];
    }
    float* out = (float*)d_out;

    dim3 grid(56 / TILE_W, 56);   // (8,56) = 448 CTAs -> 3.03/SM
    dim3 block(TILE_W, 32);       // 224 threads
    fused_pairconv_roll<<<grid, block>>>(x, W, out);
}